// round 8
// baseline (speedup 1.0000x reference)
#include <cuda_runtime.h>
#include <cstdint>

// ============================================================================
// out[M,N] = sign(x)[M,K] @ sign(w)[K,N],  M=8192, K=4096, N=4096
// Base-sm_103 path: int8 {-1,0,+1} -> mma.sync.m16n8k32.s8.s8.s32 -> f32.
// R3 -> R4: 512thr/128reg cap caused accumulator spills (1.9ms). Now 256 thr,
// warp tile 64x64, 256-reg budget, no spills.
// ============================================================================

#define M_DIM 8192
#define N_DIM 4096
#define K_DIM 4096

#define BM 128
#define BN 256
#define BK 64
#define STAGES 5
#define KITERS (K_DIM / BK)          // 64
#define M_TILES (M_DIM / BM)         // 64
#define N_TILES (N_DIM / BN)         // 16
#define THREADS 256                   // 8 warps: 2(m) x 4(n), warp tile 64x64

#define PITCH 80                      // 64B data + 16B pad: conflict-free ldmatrix
#define ASTAGE (BM * PITCH)           // 10240
#define BSTAGE (BN * PITCH)           // 20480
#define STAGE_BYTES (ASTAGE + BSTAGE) // 30720
#define SMEM_TOTAL (STAGES * STAGE_BYTES) // 153600

// ---------------------------------------------------------------------------
// Scratch (allocation-free)
// ---------------------------------------------------------------------------
__device__ __align__(128) int8_t g_xa[(size_t)M_DIM * K_DIM]; // A [M,K] int8
__device__ __align__(128) int8_t g_wt[(size_t)N_DIM * K_DIM]; // B [N,K] int8 (w^T)

// ---------------------------------------------------------------------------
// Binarization
// ---------------------------------------------------------------------------
__device__ __forceinline__ int sgn8(float v) {
    return (v > 0.0f) - (v < 0.0f);
}
__device__ __forceinline__ uint32_t pack4(float a, float b, float c, float d) {
    return (uint32_t)(uint8_t)(int8_t)sgn8(a) |
           ((uint32_t)(uint8_t)(int8_t)sgn8(b) << 8) |
           ((uint32_t)(uint8_t)(int8_t)sgn8(c) << 16) |
           ((uint32_t)(uint8_t)(int8_t)sgn8(d) << 24);
}

__global__ void binarize_x_kernel(const float4* __restrict__ x, int n16) {
    int i = blockIdx.x * blockDim.x + threadIdx.x;
    if (i < n16) {
        float4 a = x[4 * i], b = x[4 * i + 1], c = x[4 * i + 2], d = x[4 * i + 3];
        uint4 r;
        r.x = pack4(a.x, a.y, a.z, a.w);
        r.y = pack4(b.x, b.y, b.z, b.w);
        r.z = pack4(c.x, c.y, c.z, c.w);
        r.w = pack4(d.x, d.y, d.z, d.w);
        reinterpret_cast<uint4*>(g_xa)[i] = r;
    }
}

// w [K,N] f32 -> g_wt [N,K] int8 (binarize + transpose)
__global__ void binarize_wT_kernel(const float* __restrict__ w) {
    __shared__ int8_t tile[32][33];
    int n0 = blockIdx.x * 32, k0 = blockIdx.y * 32;
    int tx = threadIdx.x, ty = threadIdx.y;
#pragma unroll
    for (int j = 0; j < 4; j++) {
        int k = k0 + ty + 8 * j;
        tile[ty + 8 * j][tx] = (int8_t)sgn8(w[(size_t)k * N_DIM + n0 + tx]);
    }
    __syncthreads();
#pragma unroll
    for (int j = 0; j < 4; j++) {
        int n = n0 + ty + 8 * j;
        g_wt[(size_t)n * K_DIM + k0 + tx] = tile[tx][ty + 8 * j];
    }
}

// ---------------------------------------------------------------------------
// PTX helpers (base sm_103: cp.async, ldmatrix, mma.sync — no 'a' features)
// ---------------------------------------------------------------------------
__device__ __forceinline__ void cp16(uint32_t s, const void* g) {
    asm volatile("cp.async.cg.shared.global [%0], [%1], 16;" :: "r"(s), "l"(g));
}
__device__ __forceinline__ void cp_commit() {
    asm volatile("cp.async.commit_group;" ::: "memory");
}
__device__ __forceinline__ void cp_waitN() {
    asm volatile("cp.async.wait_group %0;" :: "n"(STAGES - 2) : "memory");
}
__device__ __forceinline__ void ldsm_x4(uint32_t* r, uint32_t addr) {
    asm volatile("ldmatrix.sync.aligned.m8n8.x4.shared.b16 {%0,%1,%2,%3}, [%4];"
                 : "=r"(r[0]), "=r"(r[1]), "=r"(r[2]), "=r"(r[3]) : "r"(addr));
}
__device__ __forceinline__ void imma(int* c, const uint32_t* a, uint32_t b0, uint32_t b1) {
    asm volatile(
        "mma.sync.aligned.m16n8k32.row.col.s32.s8.s8.s32 "
        "{%0,%1,%2,%3}, {%4,%5,%6,%7}, {%8,%9}, {%0,%1,%2,%3};"
        : "+r"(c[0]), "+r"(c[1]), "+r"(c[2]), "+r"(c[3])
        : "r"(a[0]), "r"(a[1]), "r"(a[2]), "r"(a[3]), "r"(b0), "r"(b1));
}

// ---------------------------------------------------------------------------
// GEMM: 128x256x64 CTA tile, 5-stage cp.async pipeline, 8 warps (64x64 each)
// ---------------------------------------------------------------------------
__global__ __launch_bounds__(THREADS, 1)
void gemm_kernel(float* __restrict__ out) {
    extern __shared__ char smem[];
    const uint32_t sbase = (uint32_t)__cvta_generic_to_shared(smem);
    const int tid = threadIdx.x;
    const int wid = tid >> 5;
    const int lane = tid & 31;

    const int mT = blockIdx.x & (M_TILES - 1);   // fast index: waves share B tile
    const int nT = blockIdx.x >> 6;              // / M_TILES
    const int wm = wid & 1;                      // warp m index (0..1)
    const int wn = wid >> 1;                     // warp n index (0..3)

    // --- cp.async per-thread offsets ---
    // A: 128 rows x 64B = 512 chunks -> 2/thread; B: 256 rows x 64B = 1024 -> 4/thread
    const int c16 = (tid & 3) * 16;
    const int a_r0 = tid >> 2, a_r1 = (tid + 256) >> 2;
    const int8_t* gA0 = g_xa + (size_t)(mT * BM + a_r0) * K_DIM + c16;
    const int8_t* gA1 = g_xa + (size_t)(mT * BM + a_r1) * K_DIM + c16;
    const uint32_t sA0 = sbase + a_r0 * PITCH + c16;
    const uint32_t sA1 = sbase + a_r1 * PITCH + c16;
    const int8_t* gB[4];
    uint32_t sB[4];
#pragma unroll
    for (int j = 0; j < 4; j++) {
        int br = (tid + j * 256) >> 2;
        gB[j] = g_wt + (size_t)(nT * BN + br) * K_DIM + c16;
        sB[j] = sbase + ASTAGE + br * PITCH + c16;
    }

    // --- ldmatrix per-lane offsets (within a stage) ---
    const int l8 = lane & 7, quad = lane >> 3;
    uint32_t offA[4];   // mt: 16-row chunks of the 64-row warp slice
#pragma unroll
    for (int mt = 0; mt < 4; mt++)
        offA[mt] = (uint32_t)((wm * 64 + mt * 16 + (quad & 1) * 8 + l8) * PITCH +
                              (quad >> 1) * 16);
    uint32_t offB[4];   // p: 16-col chunks of the 64-col warp slice
#pragma unroll
    for (int p = 0; p < 4; p++)
        offB[p] = (uint32_t)(ASTAGE + (wn * 64 + p * 16 + (quad >> 1) * 8 + l8) * PITCH +
                             (quad & 1) * 16);

    int c[4][8][4];     // 128 accumulators (64x64 warp tile)
#pragma unroll
    for (int mt = 0; mt < 4; mt++)
#pragma unroll
        for (int nt = 0; nt < 8; nt++)
#pragma unroll
            for (int i = 0; i < 4; i++) c[mt][nt][i] = 0;

    // --- prologue ---
#pragma unroll
    for (int s = 0; s < STAGES - 1; s++) {
        const uint32_t so = s * STAGE_BYTES;
        const int ko = s * BK;
        cp16(sA0 + so, gA0 + ko);
        cp16(sA1 + so, gA1 + ko);
#pragma unroll
        for (int j = 0; j < 4; j++) cp16(sB[j] + so, gB[j] + ko);
        cp_commit();
    }

    // --- mainloop ---
    int slot = 0;
    for (int kt = 0; kt < KITERS; kt++) {
        cp_waitN();
        __syncthreads();

        // refill the slot that just became free
        {
            const int kl = kt + STAGES - 1;
            if (kl < KITERS) {
                const int ws = (slot + STAGES - 1) % STAGES;
                const uint32_t so = ws * STAGE_BYTES;
                const int ko = kl * BK;
                cp16(sA0 + so, gA0 + ko);
                cp16(sA1 + so, gA1 + ko);
#pragma unroll
                for (int j = 0; j < 4; j++) cp16(sB[j] + so, gB[j] + ko);
            }
            cp_commit();
        }

        const uint32_t st = sbase + slot * STAGE_BYTES;
#pragma unroll
        for (int ks = 0; ks < 2; ks++) {       // two K=32 steps per stage
            uint32_t a[4][4], b[4][4];
#pragma unroll
            for (int mt = 0; mt < 4; mt++) ldsm_x4(a[mt], st + offA[mt] + ks * 32);
#pragma unroll
            for (int p = 0; p < 4; p++) ldsm_x4(b[p], st + offB[p] + ks * 32);
#pragma unroll
            for (int mt = 0; mt < 4; mt++)
#pragma unroll
                for (int p = 0; p < 4; p++) {
                    imma(c[mt][2 * p + 0], a[mt], b[p][0], b[p][1]);
                    imma(c[mt][2 * p + 1], a[mt], b[p][2], b[p][3]);
                }
        }
        if (++slot == STAGES) slot = 0;
    }

    // --- epilogue: s32 -> f32 (exact), 8B coalescible stores ---
    const int g = lane >> 2, tg = lane & 3;
    const int m_base = mT * BM + wm * 64;
    const int n_base = nT * BN + wn * 64;
#pragma unroll
    for (int mt = 0; mt < 4; mt++) {
#pragma unroll
        for (int nt = 0; nt < 8; nt++) {
            const int row = m_base + mt * 16 + g;
            const int col = n_base + nt * 8 + tg * 2;
            float2 v0 = make_float2((float)c[mt][nt][0], (float)c[mt][nt][1]);
            float2 v1 = make_float2((float)c[mt][nt][2], (float)c[mt][nt][3]);
            *reinterpret_cast<float2*>(out + (size_t)row * N_DIM + col) = v0;
            *reinterpret_cast<float2*>(out + (size_t)(row + 8) * N_DIM + col) = v1;
        }
    }
}

// ---------------------------------------------------------------------------
// Host
// ---------------------------------------------------------------------------
extern "C" void kernel_launch(void* const* d_in, const int* in_sizes, int n_in,
                              void* d_out, int out_size) {
    const float* x = (const float*)d_in[0];
    const float* w = (const float*)d_in[1];
    float* out = (float*)d_out;

    {
        int n16 = (M_DIM * K_DIM) / 16;
        binarize_x_kernel<<<n16 / 256, 256>>>((const float4*)x, n16);
    }
    binarize_wT_kernel<<<dim3(N_DIM / 32, K_DIM / 32), dim3(32, 8)>>>(w);

    static bool attr_set = false;
    if (!attr_set) {
        cudaFuncSetAttribute(gemm_kernel, cudaFuncAttributeMaxDynamicSharedMemorySize,
                             SMEM_TOTAL);
        attr_set = true;
    }
    gemm_kernel<<<M_TILES * N_TILES, THREADS, SMEM_TOTAL>>>(out);
}

// round 9
// speedup vs baseline: 2.1934x; 2.1934x over previous
#include <cuda_runtime.h>
#include <cstdint>

// ============================================================================
// out[M,N] = sign(x)[M,K] @ sign(w)[K,N],  M=8192, K=4096, N=4096
// R8 finding: s8 mma.sync on base sm_103 runs at ~256 MAC/cyc/SM (emulated).
// R9: switch to bf16 HMMA fallback (mma.sync.m16n8k16.f32.bf16.bf16.f32),
// which sass.md documents as a real tensor-pipe path on sm_103a.
// Exact: +-1/0 exact in bf16; f32 accumulation of <=4096 +-1 terms exact.
// ============================================================================

#define M_DIM 8192
#define N_DIM 4096
#define K_DIM 4096

#define BM 128
#define BN 128
#define BK 64                         // 64 bf16 = 128B per row
#define STAGES 5
#define KITERS (K_DIM / BK)           // 64
#define M_TILES (M_DIM / BM)          // 64
#define N_TILES (N_DIM / BN)          // 32
#define THREADS 256                   // 8 warps: 2(m) x 4(n), warp tile 64x32

#define PITCH 144                     // 128B data + 16B pad: conflict-free
#define ASTAGE (BM * PITCH)           // 18432
#define BSTAGE (BN * PITCH)           // 18432
#define STAGE_BYTES (ASTAGE + BSTAGE) // 36864
#define SMEM_TOTAL (STAGES * STAGE_BYTES) // 184320

// ---------------------------------------------------------------------------
// Scratch (allocation-free)
// ---------------------------------------------------------------------------
__device__ __align__(128) unsigned short g_xb[(size_t)M_DIM * K_DIM]; // A bf16 [M,K]
__device__ __align__(128) unsigned short g_wt[(size_t)N_DIM * K_DIM]; // B bf16 [N,K]
__device__ int g_dummy;

// ---------------------------------------------------------------------------
// Binarization: sign() as exact bf16 bits (+1=0x3F80, -1=0xBF80, 0=0)
// ---------------------------------------------------------------------------
__device__ __forceinline__ uint32_t sgnbits(float v) {
    uint32_t u = __float_as_uint(v);
    return (v == 0.0f) ? 0u : (0x3F80u | ((u >> 16) & 0x8000u));
}
__device__ __forceinline__ uint32_t pack2(float lo, float hi) {
    return sgnbits(lo) | (sgnbits(hi) << 16);
}

__global__ void dummy_kernel() { g_dummy = 0; }   // shifts ncu -s 5 onto the GEMM

// x [M,K] f32 -> g_xb bf16 (8 elems/thread)
__global__ void binarize_x_kernel(const float4* __restrict__ x, int n) {
    int i = blockIdx.x * blockDim.x + threadIdx.x;
    if (i < n) {
        float4 a = x[2 * i];
        float4 b = x[2 * i + 1];
        uint4 r;
        r.x = pack2(a.x, a.y);
        r.y = pack2(a.z, a.w);
        r.z = pack2(b.x, b.y);
        r.w = pack2(b.z, b.w);
        reinterpret_cast<uint4*>(g_xb)[i] = r;
    }
}

// w [K,N] f32 -> g_wt [N,K] bf16 (binarize + transpose)
__global__ void binarize_wT_kernel(const float* __restrict__ w) {
    __shared__ unsigned short tile[32][33];
    int n0 = blockIdx.x * 32, k0 = blockIdx.y * 32;
    int tx = threadIdx.x, ty = threadIdx.y;
#pragma unroll
    for (int j = 0; j < 4; j++) {
        int k = k0 + ty + 8 * j;
        tile[ty + 8 * j][tx] = (unsigned short)sgnbits(w[(size_t)k * N_DIM + n0 + tx]);
    }
    __syncthreads();
#pragma unroll
    for (int j = 0; j < 4; j++) {
        int n = n0 + ty + 8 * j;
        g_wt[(size_t)n * K_DIM + k0 + tx] = tile[tx][ty + 8 * j];
    }
}

// ---------------------------------------------------------------------------
// PTX helpers (base sm_103: cp.async, ldmatrix, mma.sync — no 'a' features)
// ---------------------------------------------------------------------------
__device__ __forceinline__ void cp16(uint32_t s, const void* g) {
    asm volatile("cp.async.cg.shared.global [%0], [%1], 16;" :: "r"(s), "l"(g));
}
__device__ __forceinline__ void cp_commit() {
    asm volatile("cp.async.commit_group;" ::: "memory");
}
__device__ __forceinline__ void cp_waitN() {
    asm volatile("cp.async.wait_group %0;" :: "n"(STAGES - 2) : "memory");
}
__device__ __forceinline__ void ldsm_x4(uint32_t* r, uint32_t addr) {
    asm volatile("ldmatrix.sync.aligned.m8n8.x4.shared.b16 {%0,%1,%2,%3}, [%4];"
                 : "=r"(r[0]), "=r"(r[1]), "=r"(r[2]), "=r"(r[3]) : "r"(addr));
}
__device__ __forceinline__ void hmma(float* c, const uint32_t* a, uint32_t b0, uint32_t b1) {
    asm volatile(
        "mma.sync.aligned.m16n8k16.row.col.f32.bf16.bf16.f32 "
        "{%0,%1,%2,%3}, {%4,%5,%6,%7}, {%8,%9}, {%0,%1,%2,%3};"
        : "+f"(c[0]), "+f"(c[1]), "+f"(c[2]), "+f"(c[3])
        : "r"(a[0]), "r"(a[1]), "r"(a[2]), "r"(a[3]), "r"(b0), "r"(b1));
}

// ---------------------------------------------------------------------------
// GEMM: 128x128x64 CTA tile, 5-stage cp.async pipeline, 8 warps (64x32 each)
// ---------------------------------------------------------------------------
__global__ __launch_bounds__(THREADS, 1)
void gemm_kernel(float* __restrict__ out) {
    extern __shared__ char smem[];
    const uint32_t sbase = (uint32_t)__cvta_generic_to_shared(smem);
    const int tid = threadIdx.x;
    const int wid = tid >> 5;
    const int lane = tid & 31;

    const int mT = blockIdx.x & (M_TILES - 1);   // fast index: waves share B tile
    const int nT = blockIdx.x >> 6;              // / M_TILES
    const int wm = wid & 1;                      // warp m (0..1), 64 rows each
    const int wn = wid >> 1;                     // warp n (0..3), 32 cols each

    // --- cp.async per-thread offsets ---
    // A: 128 rows x 128B = 1024 x 16B chunks -> 4/thread; B same
    const int c16 = (tid & 7) * 16;              // 8 threads cover one 128B row
    const int r0 = tid >> 3;                     // rows 0..31 (+32 per j)
    const unsigned short* gA[4];
    const unsigned short* gB[4];
    uint32_t sA[4], sB[4];
#pragma unroll
    for (int j = 0; j < 4; j++) {
        int r = r0 + j * 32;
        gA[j] = g_xb + (size_t)(mT * BM + r) * K_DIM + c16 / 2;
        gB[j] = g_wt + (size_t)(nT * BN + r) * K_DIM + c16 / 2;
        sA[j] = sbase + r * PITCH + c16;
        sB[j] = sbase + ASTAGE + r * PITCH + c16;
    }

    // --- ldmatrix per-lane offsets (within a stage) ---
    // A 16x16 bf16 fragments: rows = lane%16, k-half = (lane/16)*16B
    uint32_t offA[4];
#pragma unroll
    for (int mt = 0; mt < 4; mt++)
        offA[mt] = (uint32_t)((wm * 64 + mt * 16 + (lane & 15)) * PITCH +
                              (lane >> 4) * 16);
    // B [N,K]: x4 covers 16 n-rows x 16 k: n = +8*(lane/16) + lane%8,
    // k-half = ((lane>>3)&1)*16B  -> regs {c0.b0, c0.b1, c1.b0, c1.b1}
    uint32_t offB[2];
#pragma unroll
    for (int p = 0; p < 2; p++)
        offB[p] = (uint32_t)(ASTAGE +
                             (wn * 32 + p * 16 + (lane >> 4) * 8 + (lane & 7)) * PITCH +
                             ((lane >> 3) & 1) * 16);

    float c[4][4][4];    // 64 accumulators (64x32 warp tile)
#pragma unroll
    for (int mt = 0; mt < 4; mt++)
#pragma unroll
        for (int nt = 0; nt < 4; nt++)
#pragma unroll
            for (int i = 0; i < 4; i++) c[mt][nt][i] = 0.0f;

    // --- prologue ---
#pragma unroll
    for (int s = 0; s < STAGES - 1; s++) {
        const uint32_t so = s * STAGE_BYTES;
        const int ko = s * BK;
#pragma unroll
        for (int j = 0; j < 4; j++) {
            cp16(sA[j] + so, gA[j] + ko);
            cp16(sB[j] + so, gB[j] + ko);
        }
        cp_commit();
    }

    // --- mainloop ---
    int slot = 0;
    for (int kt = 0; kt < KITERS; kt++) {
        cp_waitN();
        __syncthreads();

        {   // refill freed slot
            const int kl = kt + STAGES - 1;
            if (kl < KITERS) {
                const int ws = (slot + STAGES - 1) % STAGES;
                const uint32_t so = ws * STAGE_BYTES;
                const int ko = kl * BK;
#pragma unroll
                for (int j = 0; j < 4; j++) {
                    cp16(sA[j] + so, gA[j] + ko);
                    cp16(sB[j] + so, gB[j] + ko);
                }
            }
            cp_commit();
        }

        const uint32_t st = sbase + slot * STAGE_BYTES;
#pragma unroll
        for (int ks = 0; ks < 4; ks++) {       // four K=16 steps per stage
            uint32_t a[4][4], b[2][4];
#pragma unroll
            for (int mt = 0; mt < 4; mt++) ldsm_x4(a[mt], st + offA[mt] + ks * 32);
#pragma unroll
            for (int p = 0; p < 2; p++) ldsm_x4(b[p], st + offB[p] + ks * 32);
#pragma unroll
            for (int mt = 0; mt < 4; mt++)
#pragma unroll
                for (int p = 0; p < 2; p++) {
                    hmma(c[mt][2 * p + 0], a[mt], b[p][0], b[p][1]);
                    hmma(c[mt][2 * p + 1], a[mt], b[p][2], b[p][3]);
                }
        }
        if (++slot == STAGES) slot = 0;
    }

    // --- epilogue: 8B coalescible stores ---
    const int g = lane >> 2, tg = lane & 3;
    const int m_base = mT * BM + wm * 64;
    const int n_base = nT * BN + wn * 32;
#pragma unroll
    for (int mt = 0; mt < 4; mt++) {
#pragma unroll
        for (int nt = 0; nt < 4; nt++) {
            const int row = m_base + mt * 16 + g;
            const int col = n_base + nt * 8 + tg * 2;
            float2 v0 = make_float2(c[mt][nt][0], c[mt][nt][1]);
            float2 v1 = make_float2(c[mt][nt][2], c[mt][nt][3]);
            *reinterpret_cast<float2*>(out + (size_t)row * N_DIM + col) = v0;
            *reinterpret_cast<float2*>(out + (size_t)(row + 8) * N_DIM + col) = v1;
        }
    }
}

// ---------------------------------------------------------------------------
// Host
// ---------------------------------------------------------------------------
extern "C" void kernel_launch(void* const* d_in, const int* in_sizes, int n_in,
                              void* d_out, int out_size) {
    const float* x = (const float*)d_in[0];
    const float* w = (const float*)d_in[1];
    float* out = (float*)d_out;

    dummy_kernel<<<1, 1>>>();   // shifts ncu skip-count onto the GEMM launch

    {
        int n = (M_DIM * K_DIM) / 8;
        binarize_x_kernel<<<n / 256, 256>>>((const float4*)x, n);
    }
    binarize_wT_kernel<<<dim3(N_DIM / 32, K_DIM / 32), dim3(32, 8)>>>(w);

    static bool attr_set = false;
    if (!attr_set) {
        cudaFuncSetAttribute(gemm_kernel, cudaFuncAttributeMaxDynamicSharedMemorySize,
                             SMEM_TOTAL);
        attr_set = true;
    }
    gemm_kernel<<<M_TILES * N_TILES, THREADS, SMEM_TOTAL>>>(out);
}

// round 10
// speedup vs baseline: 2.6273x; 1.1978x over previous
#include <cuda_runtime.h>
#include <cstdint>

// ============================================================================
// out[M,N] = sign(x)[M,K] @ sign(w)[K,N],  M=8192, K=4096, N=4096
// bf16 HMMA fallback path (base sm_103). R9: tensor=51.8%, occ=12.5% (1 CTA/SM,
// 2 warps/SMSP under-feed the pipe). R10: STAGES 5->3 (110.6KB smem) + reg diet
// (constant-folded addresses) => 2 CTAs/SM, 4 warps/SMSP.
// Exact: +-1/0 exact in bf16; f32 accumulation of <=4096 +-1 terms exact.
// ============================================================================

#define M_DIM 8192
#define N_DIM 4096
#define K_DIM 4096

#define BM 128
#define BN 128
#define BK 64                         // 64 bf16 = 128B per row
#define STAGES 3
#define KITERS (K_DIM / BK)           // 64
#define M_TILES (M_DIM / BM)          // 64
#define N_TILES (N_DIM / BN)          // 32
#define THREADS 256                   // 8 warps: 2(m) x 4(n), warp tile 64x32

#define PITCH 144                     // 128B data + 16B pad: conflict-free
#define ASTAGE (BM * PITCH)           // 18432
#define BSTAGE (BN * PITCH)           // 18432
#define STAGE_BYTES (ASTAGE + BSTAGE) // 36864
#define SMEM_TOTAL (STAGES * STAGE_BYTES) // 110592 -> 2 CTAs/SM

// ---------------------------------------------------------------------------
// Scratch (allocation-free)
// ---------------------------------------------------------------------------
__device__ __align__(128) unsigned short g_xb[(size_t)M_DIM * K_DIM]; // A bf16 [M,K]
__device__ __align__(128) unsigned short g_wt[(size_t)N_DIM * K_DIM]; // B bf16 [N,K]
__device__ int g_dummy;

// ---------------------------------------------------------------------------
// Binarization: sign() as exact bf16 bits (+1=0x3F80, -1=0xBF80, 0=0)
// ---------------------------------------------------------------------------
__device__ __forceinline__ uint32_t sgnbits(float v) {
    uint32_t u = __float_as_uint(v);
    return (v == 0.0f) ? 0u : (0x3F80u | ((u >> 16) & 0x8000u));
}
__device__ __forceinline__ uint32_t pack2(float lo, float hi) {
    return sgnbits(lo) | (sgnbits(hi) << 16);
}

__global__ void dummy_kernel() { g_dummy = 0; }   // keeps ncu -s 5 on the GEMM

__global__ void binarize_x_kernel(const float4* __restrict__ x, int n) {
    int i = blockIdx.x * blockDim.x + threadIdx.x;
    if (i < n) {
        float4 a = x[2 * i];
        float4 b = x[2 * i + 1];
        uint4 r;
        r.x = pack2(a.x, a.y);
        r.y = pack2(a.z, a.w);
        r.z = pack2(b.x, b.y);
        r.w = pack2(b.z, b.w);
        reinterpret_cast<uint4*>(g_xb)[i] = r;
    }
}

// w [K,N] f32 -> g_wt [N,K] bf16 (binarize + transpose)
__global__ void binarize_wT_kernel(const float* __restrict__ w) {
    __shared__ unsigned short tile[32][33];
    int n0 = blockIdx.x * 32, k0 = blockIdx.y * 32;
    int tx = threadIdx.x, ty = threadIdx.y;
#pragma unroll
    for (int j = 0; j < 4; j++) {
        int k = k0 + ty + 8 * j;
        tile[ty + 8 * j][tx] = (unsigned short)sgnbits(w[(size_t)k * N_DIM + n0 + tx]);
    }
    __syncthreads();
#pragma unroll
    for (int j = 0; j < 4; j++) {
        int n = n0 + ty + 8 * j;
        g_wt[(size_t)n * K_DIM + k0 + tx] = tile[tx][ty + 8 * j];
    }
}

// ---------------------------------------------------------------------------
// PTX helpers (base sm_103)
// ---------------------------------------------------------------------------
__device__ __forceinline__ void cp16(uint32_t s, const void* g) {
    asm volatile("cp.async.cg.shared.global [%0], [%1], 16;" :: "r"(s), "l"(g));
}
__device__ __forceinline__ void cp_commit() {
    asm volatile("cp.async.commit_group;" ::: "memory");
}
__device__ __forceinline__ void cp_waitN() {
    asm volatile("cp.async.wait_group %0;" :: "n"(STAGES - 2) : "memory");
}
__device__ __forceinline__ void ldsm_x4(uint32_t* r, uint32_t addr) {
    asm volatile("ldmatrix.sync.aligned.m8n8.x4.shared.b16 {%0,%1,%2,%3}, [%4];"
                 : "=r"(r[0]), "=r"(r[1]), "=r"(r[2]), "=r"(r[3]) : "r"(addr));
}
__device__ __forceinline__ void hmma(float* c, const uint32_t* a, uint32_t b0, uint32_t b1) {
    asm volatile(
        "mma.sync.aligned.m16n8k16.row.col.f32.bf16.bf16.f32 "
        "{%0,%1,%2,%3}, {%4,%5,%6,%7}, {%8,%9}, {%0,%1,%2,%3};"
        : "+f"(c[0]), "+f"(c[1]), "+f"(c[2]), "+f"(c[3])
        : "r"(a[0]), "r"(a[1]), "r"(a[2]), "r"(a[3]), "r"(b0), "r"(b1));
}

// ---------------------------------------------------------------------------
// GEMM: 128x128x64 CTA tile, 3-stage cp.async pipeline, 8 warps (64x32 each),
// 2 CTAs/SM (launch_bounds caps regs at 128; addresses use constant offsets)
// ---------------------------------------------------------------------------
__global__ __launch_bounds__(THREADS, 2)
void gemm_kernel(float* __restrict__ out) {
    extern __shared__ char smem[];
    const uint32_t sbase = (uint32_t)__cvta_generic_to_shared(smem);
    const int tid = threadIdx.x;
    const int wid = tid >> 5;
    const int lane = tid & 31;

    const int mT = blockIdx.x & (M_TILES - 1);   // fast index: waves share B tile
    const int nT = blockIdx.x >> 6;              // / M_TILES
    const int wm = wid & 1;                      // warp m (0..1), 64 rows each
    const int wn = wid >> 1;                     // warp n (0..3), 32 cols each

    // --- cp.async base offsets (j-strides folded as constants) ---
    const int c16 = (tid & 7) * 16;              // 8 threads cover one 128B row
    const int r0 = tid >> 3;                     // rows 0..31 (+32 per j)
    const unsigned short* gA0 = g_xb + (size_t)(mT * BM + r0) * K_DIM + c16 / 2;
    const unsigned short* gB0 = g_wt + (size_t)(nT * BN + r0) * K_DIM + c16 / 2;
    const uint32_t sA0 = sbase + r0 * PITCH + c16;
    const uint32_t sB0 = sbase + ASTAGE + r0 * PITCH + c16;
#define GJ(j) ((size_t)(j) * 32 * K_DIM)         // +32 rows in gmem (const per j)
#define SJ(j) ((uint32_t)((j) * 32 * PITCH))     // +32 rows in smem (const per j)

    // --- ldmatrix per-lane offsets (within a stage) ---
    uint32_t offA[4];
#pragma unroll
    for (int mt = 0; mt < 4; mt++)
        offA[mt] = (uint32_t)((wm * 64 + mt * 16 + (lane & 15)) * PITCH +
                              (lane >> 4) * 16);
    uint32_t offB[2];
#pragma unroll
    for (int p = 0; p < 2; p++)
        offB[p] = (uint32_t)(ASTAGE +
                             (wn * 32 + p * 16 + (lane >> 4) * 8 + (lane & 7)) * PITCH +
                             ((lane >> 3) & 1) * 16);

    float c[4][4][4];    // 64 accumulators (64x32 warp tile)
#pragma unroll
    for (int mt = 0; mt < 4; mt++)
#pragma unroll
        for (int nt = 0; nt < 4; nt++)
#pragma unroll
            for (int i = 0; i < 4; i++) c[mt][nt][i] = 0.0f;

    // --- prologue: fill STAGES-1 = 2 stages ---
#pragma unroll
    for (int s = 0; s < STAGES - 1; s++) {
        const uint32_t so = s * STAGE_BYTES;
        const int ko = s * BK;
#pragma unroll
        for (int j = 0; j < 4; j++) {
            cp16(sA0 + so + SJ(j), gA0 + ko + GJ(j));
            cp16(sB0 + so + SJ(j), gB0 + ko + GJ(j));
        }
        cp_commit();
    }

    // --- mainloop ---
    int slot = 0;
    for (int kt = 0; kt < KITERS; kt++) {
        cp_waitN();
        __syncthreads();

        {   // refill the slot consumed at kt-1
            const int kl = kt + STAGES - 1;
            if (kl < KITERS) {
                const int ws = (slot + STAGES - 1) % STAGES;
                const uint32_t so = ws * STAGE_BYTES;
                const int ko = kl * BK;
#pragma unroll
                for (int j = 0; j < 4; j++) {
                    cp16(sA0 + so + SJ(j), gA0 + ko + GJ(j));
                    cp16(sB0 + so + SJ(j), gB0 + ko + GJ(j));
                }
            }
            cp_commit();
        }

        const uint32_t st = sbase + slot * STAGE_BYTES;
#pragma unroll
        for (int ks = 0; ks < 4; ks++) {       // four K=16 steps per stage
            uint32_t a[4][4], b[2][4];
#pragma unroll
            for (int mt = 0; mt < 4; mt++) ldsm_x4(a[mt], st + offA[mt] + ks * 32);
#pragma unroll
            for (int p = 0; p < 2; p++) ldsm_x4(b[p], st + offB[p] + ks * 32);
#pragma unroll
            for (int mt = 0; mt < 4; mt++)
#pragma unroll
                for (int p = 0; p < 2; p++) {
                    hmma(c[mt][2 * p + 0], a[mt], b[p][0], b[p][1]);
                    hmma(c[mt][2 * p + 1], a[mt], b[p][2], b[p][3]);
                }
        }
        if (++slot == STAGES) slot = 0;
    }

    // --- epilogue: 8B coalescible stores ---
    const int g = lane >> 2, tg = lane & 3;
    const int m_base = mT * BM + wm * 64;
    const int n_base = nT * BN + wn * 32;
#pragma unroll
    for (int mt = 0; mt < 4; mt++) {
#pragma unroll
        for (int nt = 0; nt < 4; nt++) {
            const int row = m_base + mt * 16 + g;
            const int col = n_base + nt * 8 + tg * 2;
            float2 v0 = make_float2(c[mt][nt][0], c[mt][nt][1]);
            float2 v1 = make_float2(c[mt][nt][2], c[mt][nt][3]);
            *reinterpret_cast<float2*>(out + (size_t)row * N_DIM + col) = v0;
            *reinterpret_cast<float2*>(out + (size_t)(row + 8) * N_DIM + col) = v1;
        }
    }
}

// ---------------------------------------------------------------------------
// Host
// ---------------------------------------------------------------------------
extern "C" void kernel_launch(void* const* d_in, const int* in_sizes, int n_in,
                              void* d_out, int out_size) {
    const float* x = (const float*)d_in[0];
    const float* w = (const float*)d_in[1];
    float* out = (float*)d_out;

    dummy_kernel<<<1, 1>>>();   // keeps ncu skip-count aligned to the GEMM

    {
        int n = (M_DIM * K_DIM) / 8;
        binarize_x_kernel<<<n / 256, 256>>>((const float4*)x, n);
    }
    binarize_wT_kernel<<<dim3(N_DIM / 32, K_DIM / 32), dim3(32, 8)>>>(w);

    static bool attr_set = false;
    if (!attr_set) {
        cudaFuncSetAttribute(gemm_kernel, cudaFuncAttributeMaxDynamicSharedMemorySize,
                             SMEM_TOTAL);
        attr_set = true;
    }
    gemm_kernel<<<M_TILES * N_TILES, THREADS, SMEM_TOTAL>>>(out);
}